// round 10
// baseline (speedup 1.0000x reference)
#include <cuda_runtime.h>
#include <math.h>
#include <stdint.h>

#define H       16
#define DM      1024
#define DK      64
#define NW      16384
#define NCHUNK  256     // w-pass chunks; 64 rows each

typedef unsigned long long u64;

// ---- scratch (static __device__ arrays; no allocation) ----
__device__ __align__(16) float g_q[DM];
__device__ __align__(16) float g_a[H * DM];
__device__ __align__(16) float g_c[H];
__device__ __align__(16) float g_p[H * NW];       // unnormalized p = exp(score)
__device__ __align__(16) float g_Zpart[H * 512];  // per-scores-block exp-sum partials
__device__ __align__(16) float g_wpart[NCHUNK][H * DM];
__device__ __align__(16) float g_w[H * DM];
__device__ __align__(16) float g_x[DM];

__device__ __forceinline__ float warp_red(float v) {
#pragma unroll
    for (int o = 16; o; o >>= 1) v += __shfl_down_sync(0xffffffffu, v, o);
    return v;
}

// packed f32x2 FMA (Blackwell)
__device__ __forceinline__ u64 fma2(u64 a, u64 b, u64 c) {
    u64 d;
    asm("fma.rn.f32x2 %0, %1, %2, %3;" : "=l"(d) : "l"(a), "l"(b), "l"(c));
    return d;
}
__device__ __forceinline__ float sum2(u64 v) {
    return __uint_as_float((unsigned)v) + __uint_as_float((unsigned)(v >> 32));
}

// cp.async helpers
__device__ __forceinline__ void cp_async16(uint32_t smem_addr, const void* gptr) {
    asm volatile("cp.async.cg.shared.global [%0], [%1], 16;"
                 :: "r"(smem_addr), "l"(gptr));
}
#define CP_COMMIT()  asm volatile("cp.async.commit_group;")
#define CP_WAIT(n)   asm volatile("cp.async.wait_group %0;" :: "n"(n))

// ---- k_scores SMEM: per-warp private regions (floats) ----
// per warp: kv bufs 2 x (32 rows x 36) = 2304 fl; av bufs 2 x (16 h x 36) = 1152 fl
#define SCW_FL    3456
#define SC_BYTES  (SCW_FL * 4 * 4)       // 55296 (4 warps)

// ---- k_wpass SMEM: per-warp value bufs + shared p2 ----
// per warp: 2 bufs x (4 rows x 132) = 1056 fl; p2 u64[1024] after 8 warps
#define WPW_FL    1056
#define WP_P2FL   (8 * WPW_FL)           // 8448 floats
#define WP_BYTES  (WP_P2FL * 4 + 1024 * 8)   // 41984

// ------------------------------------------------------------------
// 1) q[i] = dot(query, Wq[i]) + bq[i].  grid 128 x 256 (warp per row)
// ------------------------------------------------------------------
__global__ void k_qproj(const float* __restrict__ query,
                        const float* __restrict__ Wq,
                        const float* __restrict__ bq) {
    __shared__ __align__(16) float qs[DM];
    const int tid = threadIdx.x;
    for (int i = tid; i < DM; i += 256) qs[i] = query[i];
    __syncthreads();
    const int w = tid >> 5, lane = tid & 31;
    const int row = blockIdx.x * 8 + w;
    const float4* wr = (const float4*)(Wq + (size_t)row * DM);
    const float4* q4 = (const float4*)qs;
    float acc = 0.f;
#pragma unroll 8
    for (int k = lane; k < DM / 4; k += 32) {
        float4 a = wr[k], b = q4[k];
        acc += a.x * b.x + a.y * b.y + a.z * b.z + a.w * b.w;
    }
    acc = warp_red(acc);
    if (lane == 0) g_q[row] = acc + bq[row];
}

// ------------------------------------------------------------------
// 2) a[h][j] = sum_d q[h*64+d]*Wk[h*64+d][j];  c[h] = sum_d q*bk
//    grid 64 x 128, two launches (hofs 0/8) so k_scores is ncu idx 3.
// ------------------------------------------------------------------
__global__ void k_aprep(const float* __restrict__ Wk,
                        const float* __restrict__ bk, int hofs) {
    const int h = hofs + (blockIdx.x >> 3), sl = blockIdx.x & 7;
    const int tid = threadIdx.x;
    __shared__ float qh[DK];
    if (tid < DK) qh[tid] = g_q[h * DK + tid];
    __syncthreads();
    const int j = sl * 128 + tid;
    const float* base = Wk + (size_t)(h * DK) * DM + j;
    float acc = 0.f;
#pragma unroll 8
    for (int d = 0; d < DK; d++) acc += qh[d] * base[(size_t)d * DM];
    g_a[h * DM + j] = acc;
    if (sl == 0 && tid < 32) {
        float c = 0.f;
        for (int d = tid; d < DK; d += 32) c += qh[d] * bk[h * DK + d];
        c = warp_red(c);
        if (tid == 0) g_c[h] = c;
    }
}

// ------------------------------------------------------------------
// 3) k_scores: warp-autonomous. grid 512 x 128 (4 warps), 4 blocks/SM.
//    Block = 32 rows. Warp w owns j-slice [w*256, w*256+256), lane=row.
//    8 subtiles of 32 j; key + a both cp.async-streamed into private
//    double buffers; NO __syncthreads in the steady state.
// ------------------------------------------------------------------
__global__ void __launch_bounds__(128, 4) k_scores(const float* __restrict__ key) {
    extern __shared__ __align__(16) float smem[];
    const int tid = threadIdx.x;
    const int w = tid >> 5, lane = tid & 31;
    const int n0 = blockIdx.x * 32;
    const int j0 = w * 256;

    const uint32_t wbase = (uint32_t)__cvta_generic_to_shared(smem) + w * SCW_FL * 4;
    const uint32_t kvb[2] = { wbase, wbase + 1152 * 4 };
    const uint32_t avb[2] = { wbase + 2304 * 4, wbase + (2304 + 576) * 4 };

    // staging maps (verified conflict-free with pitch 36)
    const float* krow = key + (size_t)(n0 + lane) * DM + j0;   // lane stages its row
    const int ah = lane >> 1, ahalf = (lane & 1) * 16;         // 2 lanes per head
    const float* arow = g_a + ah * DM + j0 + ahalf;

#define SC_ISSUE(s, t)                                                          \
    do {                                                                        \
        _Pragma("unroll")                                                       \
        for (int jf = 0; jf < 8; jf++)                                          \
            cp_async16(kvb[s] + (lane * 36 + jf * 4) * 4, krow + (t) * 32 + jf * 4); \
        _Pragma("unroll")                                                       \
        for (int k = 0; k < 4; k++)                                             \
            cp_async16(avb[s] + (ah * 36 + ahalf + k * 4) * 4, arow + (t) * 32 + k * 4); \
        CP_COMMIT();                                                            \
    } while (0)

    SC_ISSUE(0, 0);
    SC_ISSUE(1, 1);

    u64 acc[16];
#pragma unroll
    for (int h = 0; h < 16; h++) acc[h] = 0ull;

#pragma unroll
    for (int t = 0; t < 8; t++) {
        if (t == 7) { CP_WAIT(0); } else { CP_WAIT(1); }
        __syncwarp();
        const float* kt = smem + w * SCW_FL + (t & 1) * 1152;
        const float* at = smem + w * SCW_FL + 2304 + (t & 1) * 576;
#pragma unroll
        for (int jf = 0; jf < 8; jf++) {
            const ulonglong2 kv = *(const ulonglong2*)&kt[lane * 36 + jf * 4];
#pragma unroll
            for (int h = 0; h < 16; h++) {
                const ulonglong2 av = *(const ulonglong2*)&at[h * 36 + jf * 4];
                acc[h] = fma2(kv.x, av.x, acc[h]);
                acc[h] = fma2(kv.y, av.y, acc[h]);
            }
        }
        if (t < 6) SC_ISSUE(t & 1, t + 2);
    }
#undef SC_ISSUE

    // epilogue: cross-warp j-reduction (2 barriers total per block)
    __syncthreads();
    float* red = smem;                       // 16 h x 4 w x 32 rows = 2048 fl
#pragma unroll
    for (int h = 0; h < 16; h++)
        red[h * 128 + w * 32 + lane] = sum2(acc[h]);
    __syncthreads();
#pragma unroll
    for (int s = 0; s < 4; s++) {
        const int hh = w + s * 4;            // warp w handles heads w, w+4, w+8, w+12
        float v = g_c[hh];
#pragma unroll
        for (int ww = 0; ww < 4; ww++) v += red[hh * 128 + ww * 32 + lane];
        const float e = __expf(v);
        g_p[hh * NW + n0 + lane] = e;
        float z = warp_red(e);
        if (lane == 0) g_Zpart[hh * 512 + blockIdx.x] = z;
    }
}

// ------------------------------------------------------------------
// 4) k_wpass: warp-autonomous. grid 256 x 256 (2 blocks/SM).
//    Block = 64 rows. Warp w owns float cols [w*128, w*128+128).
//    16 private 4-row value tiles via cp.async; one barrier (p2 load).
// ------------------------------------------------------------------
__global__ void __launch_bounds__(256, 2) k_wpass(const float* __restrict__ value) {
    extern __shared__ __align__(16) float smem[];
    u64* p2 = (u64*)(smem + WP_P2FL);
    const int tid = threadIdx.x;
    const int w = tid >> 5, lane = tid & 31;
    const int n0 = blockIdx.x * 64;

    const uint32_t wbase = (uint32_t)__cvta_generic_to_shared(smem) + w * WPW_FL * 4;
    const uint32_t vb[2] = { wbase, wbase + 528 * 4 };

    // staging: lane -> row r = lane&3, 64B chunk c = lane>>2 (pitch 132: conflict-free)
    const int vr = lane & 3, vc = lane >> 2;
    const float* vsrc = value + (size_t)(n0 + vr) * DM + w * 128 + vc * 16;

#define WP_ISSUE(s, t)                                                          \
    do {                                                                        \
        _Pragma("unroll")                                                       \
        for (int k = 0; k < 4; k++)                                             \
            cp_async16(vb[s] + (vr * 132 + vc * 16 + k * 4) * 4,                \
                       vsrc + (size_t)(t) * 4 * DM + k * 4);                    \
        CP_COMMIT();                                                            \
    } while (0)

    WP_ISSUE(0, 0);
    WP_ISSUE(1, 1);

    // p2: load + dup-pack (overlaps in-flight cp.async); single barrier
    for (int i = tid; i < H * 64; i += 256) {
        const int h = i >> 6, n = i & 63;
        const unsigned b = __float_as_uint(g_p[h * NW + n0 + n]);
        p2[i] = ((u64)b << 32) | b;
    }
    __syncthreads();

    ulonglong2 acc[H];
#pragma unroll
    for (int h = 0; h < H; h++) acc[h] = make_ulonglong2(0ull, 0ull);

#pragma unroll
    for (int t = 0; t < 16; t++) {
        if (t == 15) { CP_WAIT(0); } else { CP_WAIT(1); }
        __syncwarp();
        const float* vs = smem + w * WPW_FL + (t & 1) * 528;
        const ulonglong2 v0 = *(const ulonglong2*)&vs[0 * 132 + lane * 4];
        const ulonglong2 v1 = *(const ulonglong2*)&vs[1 * 132 + lane * 4];
        const ulonglong2 v2 = *(const ulonglong2*)&vs[2 * 132 + lane * 4];
        const ulonglong2 v3 = *(const ulonglong2*)&vs[3 * 132 + lane * 4];
#pragma unroll
        for (int h = 0; h < H; h++) {
            const u64* ph = &p2[h * 64 + t * 4];
            const ulonglong2 pA = *(const ulonglong2*)(ph + 0);   // rows 0,1
            const ulonglong2 pB = *(const ulonglong2*)(ph + 2);   // rows 2,3
            acc[h].x = fma2(pA.x, v0.x, acc[h].x); acc[h].y = fma2(pA.x, v0.y, acc[h].y);
            acc[h].x = fma2(pA.y, v1.x, acc[h].x); acc[h].y = fma2(pA.y, v1.y, acc[h].y);
            acc[h].x = fma2(pB.x, v2.x, acc[h].x); acc[h].y = fma2(pB.x, v2.y, acc[h].y);
            acc[h].x = fma2(pB.y, v3.x, acc[h].x); acc[h].y = fma2(pB.y, v3.y, acc[h].y);
        }
        if (t < 14) WP_ISSUE(t & 1, t + 2);
    }
#undef WP_ISSUE

    ulonglong2* wp = (ulonglong2*)&g_wpart[blockIdx.x][0];
#pragma unroll
    for (int h = 0; h < H; h++) wp[h * 256 + w * 32 + lane] = acc[h];
}

// ------------------------------------------------------------------
// 5) w[i] = (sum_c wpart[c][i]) / Z[h].  grid 512 x 256, float4.
// ------------------------------------------------------------------
__global__ void k_wreduce() {
    __shared__ __align__(16) float4 part[256];
    __shared__ float zs;
    const int tid = threadIdx.x;
    const int cseg = tid >> 3;                // 0..31 (8 chunks each)
    const int col  = tid & 7;                 // 0..7
    const int b = blockIdx.x;
    const int h = b >> 5;                     // 32 blocks per head
    const int f4col = b * 8 + col;

    const float4* wp4 = (const float4*)&g_wpart[0][0];
    float4 acc = make_float4(0.f, 0.f, 0.f, 0.f);
#pragma unroll
    for (int k = 0; k < 8; k++) {
        const float4 v = wp4[(size_t)(cseg * 8 + k) * 4096 + f4col];
        acc.x += v.x; acc.y += v.y; acc.z += v.z; acc.w += v.w;
    }
    part[tid] = acc;

    if (tid < 32) {
        const float4* zp = (const float4*)(g_Zpart + h * 512);
        float z = 0.f;
#pragma unroll
        for (int k = 0; k < 4; k++) {
            const float4 v = zp[tid * 4 + k];
            z += v.x + v.y + v.z + v.w;
        }
        z = warp_red(z);
        if (tid == 0) zs = z;
    }
    __syncthreads();

    if (tid < 8) {
        float4 s = part[tid];
#pragma unroll
        for (int k = 1; k < 32; k++) {
            const float4 v = part[k * 8 + tid];
            s.x += v.x; s.y += v.y; s.z += v.z; s.w += v.w;
        }
        const float inv = 1.0f / zs;
        s.x *= inv; s.y *= inv; s.z *= inv; s.w *= inv;
        ((float4*)g_w)[b * 8 + tid] = s;
    }
}

// ------------------------------------------------------------------
// 6) x[i] = dot(w[h], Wv[i]) + bv[i], h = i/64.  grid 128 x 256.
// ------------------------------------------------------------------
__global__ void k_xproj(const float* __restrict__ Wv,
                        const float* __restrict__ bv) {
    __shared__ __align__(16) float ws[DM];
    const int tid = threadIdx.x;
    const int h = blockIdx.x >> 3;
    for (int i = tid; i < DM; i += 256) ws[i] = g_w[h * DM + i];
    __syncthreads();
    const int w = tid >> 5, lane = tid & 31;
    const int row = blockIdx.x * 8 + w;
    const float4* wr = (const float4*)(Wv + (size_t)row * DM);
    const float4* q4 = (const float4*)ws;
    float acc = 0.f;
#pragma unroll 8
    for (int k = lane; k < DM / 4; k += 32) {
        float4 a = wr[k], b = q4[k];
        acc += a.x * b.x + a.y * b.y + a.z * b.z + a.w * b.w;
    }
    acc = warp_red(acc);
    if (lane == 0) g_x[row] = acc + bv[row];
}

// ------------------------------------------------------------------
// 7) out[i] = dot(x, Wo[i]) + bo[i].  grid 128 x 256.
// ------------------------------------------------------------------
__global__ void k_out(const float* __restrict__ Wo,
                      const float* __restrict__ bo,
                      float* __restrict__ out) {
    __shared__ __align__(16) float xs[DM];
    const int tid = threadIdx.x;
    for (int i = tid; i < DM; i += 256) xs[i] = g_x[i];
    __syncthreads();
    const int w = tid >> 5, lane = tid & 31;
    const int row = blockIdx.x * 8 + w;
    const float4* wr = (const float4*)(Wo + (size_t)row * DM);
    const float4* q4 = (const float4*)xs;
    float acc = 0.f;
#pragma unroll 8
    for (int k = lane; k < DM / 4; k += 32) {
        float4 a = wr[k], b = q4[k];
        acc += a.x * b.x + a.y * b.y + a.z * b.z + a.w * b.w;
    }
    acc = warp_red(acc);
    if (lane == 0) out[row] = acc + bo[row];
}

// ------------------------------------------------------------------
extern "C" void kernel_launch(void* const* d_in, const int* in_sizes, int n_in,
                              void* d_out, int out_size) {
    (void)in_sizes; (void)n_in; (void)out_size;
    const float* query = (const float*)d_in[0];
    const float* key   = (const float*)d_in[1];
    const float* value = (const float*)d_in[2];
    const float* Wq    = (const float*)d_in[3];
    const float* bq    = (const float*)d_in[4];
    const float* Wk    = (const float*)d_in[5];
    const float* bk    = (const float*)d_in[6];
    const float* Wv    = (const float*)d_in[7];
    const float* bv    = (const float*)d_in[8];
    const float* Wo    = (const float*)d_in[9];
    const float* bo    = (const float*)d_in[10];
    float* out = (float*)d_out;

    cudaFuncSetAttribute(k_scores, cudaFuncAttributeMaxDynamicSharedMemorySize,
                         SC_BYTES);
    cudaFuncSetAttribute(k_wpass, cudaFuncAttributeMaxDynamicSharedMemorySize,
                         WP_BYTES);

    k_qproj  <<<128, 256>>>(query, Wq, bq);          // idx 0
    k_aprep  <<<64, 128>>>(Wk, bk, 0);               // idx 1
    k_aprep  <<<64, 128>>>(Wk, bk, 8);               // idx 2
    k_scores <<<512, 128, SC_BYTES>>>(key);          // idx 3  <- ncu window
    k_wpass  <<<NCHUNK, 256, WP_BYTES>>>(value);     // idx 4
    k_wreduce<<<512, 256>>>();                       // idx 5
    k_xproj  <<<128, 256>>>(Wv, bv);                 // idx 6
    k_out    <<<128, 256>>>(Wo, bo, out);            // idx 7
}

// round 11
// speedup vs baseline: 1.0930x; 1.0930x over previous
#include <cuda_runtime.h>
#include <math.h>
#include <stdint.h>

#define H       16
#define DM      1024
#define DK      64
#define NW      16384
#define NCHUNK  256     // w-pass chunks; 64 rows each

typedef unsigned long long u64;

// ---- scratch (static __device__ arrays; no allocation) ----
__device__ __align__(16) float g_q[DM];
__device__ __align__(16) float g_a[H * DM];
__device__ __align__(16) float g_c[H];
__device__ __align__(16) float g_p[H * NW];       // unnormalized p = exp(score)
__device__ __align__(16) float g_Zpart[H * 512];  // per-scores-block exp-sum partials
__device__ __align__(16) float g_wpart[NCHUNK][H * DM];
__device__ __align__(16) float g_w[H * DM];
__device__ __align__(16) float g_x[DM];

__device__ __forceinline__ float warp_red(float v) {
#pragma unroll
    for (int o = 16; o; o >>= 1) v += __shfl_down_sync(0xffffffffu, v, o);
    return v;
}

// packed f32x2 FMA (Blackwell)
__device__ __forceinline__ u64 fma2(u64 a, u64 b, u64 c) {
    u64 d;
    asm("fma.rn.f32x2 %0, %1, %2, %3;" : "=l"(d) : "l"(a), "l"(b), "l"(c));
    return d;
}
__device__ __forceinline__ float sum2(u64 v) {
    return __uint_as_float((unsigned)v) + __uint_as_float((unsigned)(v >> 32));
}

// cp.async helpers
__device__ __forceinline__ void cp_async16(uint32_t smem_addr, const void* gptr) {
    asm volatile("cp.async.cg.shared.global [%0], [%1], 16;"
                 :: "r"(smem_addr), "l"(gptr));
}
#define CP_COMMIT()  asm volatile("cp.async.commit_group;")
#define CP_WAIT(n)   asm volatile("cp.async.wait_group %0;" :: "n"(n))

// ---- k_scores SMEM (floats): 3-stage, 64-j tiles ----
// kt stage: 32 rows x 68 = 2176 fl; at stage: 16 h x 68 = 1088 fl
#define SCC_KT(s)  ((s) * 2176)
#define SCC_AT(s)  (6528 + (s) * 1088)
#define SCC_FLOATS 9792
#define SCC_BYTES  (SCC_FLOATS * 4)     // 39168 -> 4 blocks/SM

// ---- k_wpass SMEM: 3-stage x 4-row value tiles + p2 ----
#define WPV(s)     ((s) * 4096)         // 4 rows x 1024 floats per stage
#define WP_P2      12288                // u64[1024] after the 3 stages
#define WP_BYTES   (12288 * 4 + 1024 * 8)   // 57344 -> 2 blocks/SM (512 thr)

// ------------------------------------------------------------------
// 1) q[i] = dot(query, Wq[i]) + bq[i].  grid 128 x 256 (warp per row)
// ------------------------------------------------------------------
__global__ void k_qproj(const float* __restrict__ query,
                        const float* __restrict__ Wq,
                        const float* __restrict__ bq) {
    __shared__ __align__(16) float qs[DM];
    const int tid = threadIdx.x;
    for (int i = tid; i < DM; i += 256) qs[i] = query[i];
    __syncthreads();
    const int w = tid >> 5, lane = tid & 31;
    const int row = blockIdx.x * 8 + w;
    const float4* wr = (const float4*)(Wq + (size_t)row * DM);
    const float4* q4 = (const float4*)qs;
    float acc = 0.f;
#pragma unroll 8
    for (int k = lane; k < DM / 4; k += 32) {
        float4 a = wr[k], b = q4[k];
        acc += a.x * b.x + a.y * b.y + a.z * b.z + a.w * b.w;
    }
    acc = warp_red(acc);
    if (lane == 0) g_q[row] = acc + bq[row];
}

// ------------------------------------------------------------------
// 2) a[h][j] = sum_d q[h*64+d]*Wk[h*64+d][j];  c[h] = sum_d q*bk
//    grid 64 x 128, two launches (hofs 0/8) so k_scores is ncu idx 3.
// ------------------------------------------------------------------
__global__ void k_aprep(const float* __restrict__ Wk,
                        const float* __restrict__ bk, int hofs) {
    const int h = hofs + (blockIdx.x >> 3), sl = blockIdx.x & 7;
    const int tid = threadIdx.x;
    __shared__ float qh[DK];
    if (tid < DK) qh[tid] = g_q[h * DK + tid];
    __syncthreads();
    const int j = sl * 128 + tid;
    const float* base = Wk + (size_t)(h * DK) * DM + j;
    float acc = 0.f;
#pragma unroll 8
    for (int d = 0; d < DK; d++) acc += qh[d] * base[(size_t)d * DM];
    g_a[h * DM + j] = acc;
    if (sl == 0 && tid < 32) {
        float c = 0.f;
        for (int d = tid; d < DK; d += 32) c += qh[d] * bk[h * DK + d];
        c = warp_red(c);
        if (tid == 0) g_c[h] = c;
    }
}

// ------------------------------------------------------------------
// 3) k_scores: p[h][n] = exp(dot(key[n], a[h]) + c[h]), Z partials.
//    grid 512 x 256, __launch_bounds__(256,4) -> 32 warps/SM.
//    Warp = (head-half, 16-j slice): acc = 8 x u64 = 16 regs.
//    16 tiles of 64 j; 3-stage cp.async pipeline; 1 barrier/tile.
// ------------------------------------------------------------------
__global__ void __launch_bounds__(256, 4) k_scores(const float* __restrict__ key) {
    extern __shared__ __align__(16) float smem[];
    const int tid = threadIdx.x;
    const int w = tid >> 5, lane = tid & 31;
    const int hh = (w & 1) * 8;          // head half base: 0 or 8
    const int js = (w >> 1) & 3;         // j-slice: [js*16, js*16+16) in 64-j tile
    const int n0 = blockIdx.x * 32;

    const uint32_t smem_u32 = (uint32_t)__cvta_generic_to_shared(smem);

    // staging maps
    const int kr  = tid >> 3;            // key row 0..31
    const int kc0 = (tid & 7) * 2;       // key f4 col base (2 per thread)
    const int ar  = tid >> 4;            // a head 0..15
    const int ac  = tid & 15;            // a f4 col

    const float* krow = key + (size_t)(n0 + kr) * DM;
    const float4* ga4 = (const float4*)g_a;

#define SC_ISSUE(st, tt)                                                        \
    do {                                                                        \
        const uint32_t dk = smem_u32 + SCC_KT(st) * 4;                          \
        const uint32_t da = smem_u32 + SCC_AT(st) * 4;                          \
        cp_async16(dk + (kr * 68 + kc0 * 4) * 4,       krow + (tt) * 64 + kc0 * 4);     \
        cp_async16(dk + (kr * 68 + (kc0 + 1) * 4) * 4, krow + (tt) * 64 + (kc0 + 1) * 4);\
        cp_async16(da + (ar * 68 + ac * 4) * 4,  ga4 + ar * 256 + (tt) * 16 + ac);      \
        CP_COMMIT();                                                            \
    } while (0)

    SC_ISSUE(0, 0);
    SC_ISSUE(1, 1);

    u64 acc[8];
#pragma unroll
    for (int i = 0; i < 8; i++) acc[i] = 0ull;

#pragma unroll
    for (int t = 0; t < 16; t++) {
        if (t == 15) { CP_WAIT(0); } else { CP_WAIT(1); }
        __syncthreads();
        const int s = t % 3;
        const float* ktb = smem + SCC_KT(s);
        const float* atb = smem + SCC_AT(s);
#pragma unroll
        for (int q = 0; q < 4; q++) {
            const int j = js * 16 + q * 4;
            const ulonglong2 kv = *(const ulonglong2*)&ktb[lane * 68 + j];
#pragma unroll
            for (int i = 0; i < 8; i++) {
                const ulonglong2 av = *(const ulonglong2*)&atb[(hh + i) * 68 + j];
                acc[i] = fma2(kv.x, av.x, acc[i]);
                acc[i] = fma2(kv.y, av.y, acc[i]);
            }
        }
        if (t < 14) {
            const int sn = (t + 2) % 3;
            SC_ISSUE(sn, t + 2);
        }
    }
#undef SC_ISSUE

    // epilogue: reduce 4 j-slice partials per (head,row)
    __syncthreads();
    float* red = smem;                       // 16 h x 4 js x 32 rows = 2048 fl
#pragma unroll
    for (int i = 0; i < 8; i++)
        red[(hh + i) * 128 + js * 32 + lane] = sum2(acc[i]);
    __syncthreads();
    const int h0 = tid >> 5;                 // warp id 0..7
    const int r  = tid & 31;
#pragma unroll
    for (int s = 0; s < 2; s++) {
        const int hhh = h0 + 8 * s;
        float v = g_c[hhh];
#pragma unroll
        for (int q4s = 0; q4s < 4; q4s++) v += red[hhh * 128 + q4s * 32 + r];
        const float e = __expf(v);
        g_p[hhh * NW + n0 + r] = e;
        float z = warp_red(e);
        if (r == 0) g_Zpart[hhh * 512 + blockIdx.x] = z;
    }
}

// ------------------------------------------------------------------
// 4) k_wpass: wpart[c][h][j] = sum_{n in chunk} p[h][n]*value[n][j].
//    grid 256 x 512, __launch_bounds__(512,2) -> 32 warps/SM.
//    Thread = (f4 col, head-half): acc = 8 x ulonglong2 = 32 regs.
//    16 tiles of 4 rows via 3-stage cp.async; 2-row compute steps.
// ------------------------------------------------------------------
__global__ void __launch_bounds__(512, 2) k_wpass(const float* __restrict__ value) {
    extern __shared__ __align__(16) float smem[];
    u64* p2 = (u64*)(smem + WP_P2);
    const int tid = threadIdx.x;
    const int half = tid >> 8;               // head half: 0 or 8 heads base
    const int col = tid & 255;               // f4 column 0..255
    const int hb = half * 8;
    const int n0 = blockIdx.x * 64;

    const uint32_t smem_u32 = (uint32_t)__cvta_generic_to_shared(smem);

    // staging: vr = row 0..3, vcf = f4-pair col 0..127 (2 cp.async16/thread)
    const int vr = tid >> 7;
    const int vcf = (tid & 127) * 2;
    const float* vsrc = value + (size_t)(n0 + vr) * DM + vcf * 4;

#define WP_ISSUE(st, tt)                                                        \
    do {                                                                        \
        const uint32_t dv = smem_u32 + WPV(st) * 4;                             \
        cp_async16(dv + (vr * 1024 + vcf * 4) * 4,       vsrc + (size_t)(tt) * 4 * DM);     \
        cp_async16(dv + (vr * 1024 + (vcf + 1) * 4) * 4, vsrc + (size_t)(tt) * 4 * DM + 4); \
        CP_COMMIT();                                                            \
    } while (0)

    WP_ISSUE(0, 0);
    WP_ISSUE(1, 1);

    // p2: load + dup-pack (overlaps in-flight cp.async)
    for (int i = tid; i < H * 64; i += 512) {
        const int h = i >> 6, n = i & 63;
        const unsigned b = __float_as_uint(g_p[h * NW + n0 + n]);
        p2[i] = ((u64)b << 32) | b;
    }

    ulonglong2 acc[8];
#pragma unroll
    for (int i = 0; i < 8; i++) acc[i] = make_ulonglong2(0ull, 0ull);

#pragma unroll
    for (int t = 0; t < 16; t++) {
        if (t == 15) { CP_WAIT(0); } else { CP_WAIT(1); }
        __syncthreads();    // also covers initial p2 visibility at t=0
        const float* vs = smem + WPV(t % 3);
#pragma unroll
        for (int sub = 0; sub < 2; sub++) {
            const ulonglong2 v0 = *(const ulonglong2*)&vs[(sub * 2 + 0) * 1024 + col * 4];
            const ulonglong2 v1 = *(const ulonglong2*)&vs[(sub * 2 + 1) * 1024 + col * 4];
#pragma unroll
            for (int i = 0; i < 8; i++) {
                // p pair for rows (t*4+sub*2, +1): broadcast LDS.128
                const ulonglong2 pA = *(const ulonglong2*)&p2[(hb + i) * 64 + t * 4 + sub * 2];
                acc[i].x = fma2(pA.x, v0.x, acc[i].x);
                acc[i].y = fma2(pA.x, v0.y, acc[i].y);
                acc[i].x = fma2(pA.y, v1.x, acc[i].x);
                acc[i].y = fma2(pA.y, v1.y, acc[i].y);
            }
        }
        if (t < 14) WP_ISSUE((t + 2) % 3, t + 2);
    }
#undef WP_ISSUE

    ulonglong2* wp = (ulonglong2*)&g_wpart[blockIdx.x][0];
#pragma unroll
    for (int i = 0; i < 8; i++) wp[(hb + i) * 256 + col] = acc[i];
}

// ------------------------------------------------------------------
// 5) w[i] = (sum_c wpart[c][i]) / Z[h].  grid 512 x 256, float4.
// ------------------------------------------------------------------
__global__ void k_wreduce() {
    __shared__ __align__(16) float4 part[256];
    __shared__ float zs;
    const int tid = threadIdx.x;
    const int cseg = tid >> 3;                // 0..31 (8 chunks each)
    const int col  = tid & 7;                 // 0..7
    const int b = blockIdx.x;
    const int h = b >> 5;                     // 32 blocks per head
    const int f4col = b * 8 + col;

    const float4* wp4 = (const float4*)&g_wpart[0][0];
    float4 acc = make_float4(0.f, 0.f, 0.f, 0.f);
#pragma unroll
    for (int k = 0; k < 8; k++) {
        const float4 v = wp4[(size_t)(cseg * 8 + k) * 4096 + f4col];
        acc.x += v.x; acc.y += v.y; acc.z += v.z; acc.w += v.w;
    }
    part[tid] = acc;

    if (tid < 32) {
        const float4* zp = (const float4*)(g_Zpart + h * 512);
        float z = 0.f;
#pragma unroll
        for (int k = 0; k < 4; k++) {
            const float4 v = zp[tid * 4 + k];
            z += v.x + v.y + v.z + v.w;
        }
        z = warp_red(z);
        if (tid == 0) zs = z;
    }
    __syncthreads();

    if (tid < 8) {
        float4 s = part[tid];
#pragma unroll
        for (int k = 1; k < 32; k++) {
            const float4 v = part[k * 8 + tid];
            s.x += v.x; s.y += v.y; s.z += v.z; s.w += v.w;
        }
        const float inv = 1.0f / zs;
        s.x *= inv; s.y *= inv; s.z *= inv; s.w *= inv;
        ((float4*)g_w)[b * 8 + tid] = s;
    }
}

// ------------------------------------------------------------------
// 6) x[i] = dot(w[h], Wv[i]) + bv[i], h = i/64.  grid 128 x 256.
// ------------------------------------------------------------------
__global__ void k_xproj(const float* __restrict__ Wv,
                        const float* __restrict__ bv) {
    __shared__ __align__(16) float ws[DM];
    const int tid = threadIdx.x;
    const int h = blockIdx.x >> 3;
    for (int i = tid; i < DM; i += 256) ws[i] = g_w[h * DM + i];
    __syncthreads();
    const int w = tid >> 5, lane = tid & 31;
    const int row = blockIdx.x * 8 + w;
    const float4* wr = (const float4*)(Wv + (size_t)row * DM);
    const float4* q4 = (const float4*)ws;
    float acc = 0.f;
#pragma unroll 8
    for (int k = lane; k < DM / 4; k += 32) {
        float4 a = wr[k], b = q4[k];
        acc += a.x * b.x + a.y * b.y + a.z * b.z + a.w * b.w;
    }
    acc = warp_red(acc);
    if (lane == 0) g_x[row] = acc + bv[row];
}

// ------------------------------------------------------------------
// 7) out[i] = dot(x, Wo[i]) + bo[i].  grid 128 x 256.
// ------------------------------------------------------------------
__global__ void k_out(const float* __restrict__ Wo,
                      const float* __restrict__ bo,
                      float* __restrict__ out) {
    __shared__ __align__(16) float xs[DM];
    const int tid = threadIdx.x;
    for (int i = tid; i < DM; i += 256) xs[i] = g_x[i];
    __syncthreads();
    const int w = tid >> 5, lane = tid & 31;
    const int row = blockIdx.x * 8 + w;
    const float4* wr = (const float4*)(Wo + (size_t)row * DM);
    const float4* q4 = (const float4*)xs;
    float acc = 0.f;
#pragma unroll 8
    for (int k = lane; k < DM / 4; k += 32) {
        float4 a = wr[k], b = q4[k];
        acc += a.x * b.x + a.y * b.y + a.z * b.z + a.w * b.w;
    }
    acc = warp_red(acc);
    if (lane == 0) out[row] = acc + bo[row];
}

// ------------------------------------------------------------------
extern "C" void kernel_launch(void* const* d_in, const int* in_sizes, int n_in,
                              void* d_out, int out_size) {
    (void)in_sizes; (void)n_in; (void)out_size;
    const float* query = (const float*)d_in[0];
    const float* key   = (const float*)d_in[1];
    const float* value = (const float*)d_in[2];
    const float* Wq    = (const float*)d_in[3];
    const float* bq    = (const float*)d_in[4];
    const float* Wk    = (const float*)d_in[5];
    const float* bk    = (const float*)d_in[6];
    const float* Wv    = (const float*)d_in[7];
    const float* bv    = (const float*)d_in[8];
    const float* Wo    = (const float*)d_in[9];
    const float* bo    = (const float*)d_in[10];
    float* out = (float*)d_out;

    cudaFuncSetAttribute(k_scores, cudaFuncAttributeMaxDynamicSharedMemorySize,
                         SCC_BYTES);
    cudaFuncSetAttribute(k_wpass, cudaFuncAttributeMaxDynamicSharedMemorySize,
                         WP_BYTES);

    k_qproj  <<<128, 256>>>(query, Wq, bq);          // idx 0
    k_aprep  <<<64, 128>>>(Wk, bk, 0);               // idx 1
    k_aprep  <<<64, 128>>>(Wk, bk, 8);               // idx 2
    k_scores <<<512, 256, SCC_BYTES>>>(key);         // idx 3  <- ncu window
    k_wpass  <<<NCHUNK, 512, WP_BYTES>>>(value);     // idx 4
    k_wreduce<<<512, 256>>>();                       // idx 5
    k_xproj  <<<128, 256>>>(Wv, bv);                 // idx 6
    k_out    <<<128, 256>>>(Wo, bo, out);            // idx 7
}

// round 12
// speedup vs baseline: 1.1246x; 1.0289x over previous
#include <cuda_runtime.h>
#include <math.h>
#include <stdint.h>

#define H       16
#define DM      1024
#define DK      64
#define NW      16384
#define NCHUNK  256     // attn blocks; 64 rows each

typedef unsigned long long u64;

// ---- scratch (static __device__ arrays; no allocation) ----
__device__ __align__(16) float g_q[DM];
__device__ __align__(16) float g_a[H * DM];
__device__ __align__(16) float g_c[H];
__device__ __align__(16) float g_Zpart[H * 512];
__device__ __align__(16) float g_wpart[NCHUNK][H * DM];
__device__ __align__(16) float g_w[H * DM];
__device__ __align__(16) float g_x[DM];

__device__ __forceinline__ float warp_red(float v) {
#pragma unroll
    for (int o = 16; o; o >>= 1) v += __shfl_down_sync(0xffffffffu, v, o);
    return v;
}

// packed f32x2 FMA (Blackwell)
__device__ __forceinline__ u64 fma2(u64 a, u64 b, u64 c) {
    u64 d;
    asm("fma.rn.f32x2 %0, %1, %2, %3;" : "=l"(d) : "l"(a), "l"(b), "l"(c));
    return d;
}
__device__ __forceinline__ float sum2(u64 v) {
    return __uint_as_float((unsigned)v) + __uint_as_float((unsigned)(v >> 32));
}

// cp.async helpers
__device__ __forceinline__ void cp_async16(uint32_t smem_addr, const void* gptr) {
    asm volatile("cp.async.cg.shared.global [%0], [%1], 16;"
                 :: "r"(smem_addr), "l"(gptr));
}
#define CP_COMMIT()  asm volatile("cp.async.commit_group;")
#define CP_WAIT(n)   asm volatile("cp.async.wait_group %0;" :: "n"(n))

// ---- k_attn SMEM (floats): 4-stage ring of (key tile, a tile) + p2 ----
// kt stage: 32 rows x 132 = 4224 fl; at stage: 16 h x 132 = 2112 fl
#define AT_KT(s)  ((s) * 4224)
#define AT_AT(s)  (16896 + (s) * 2112)
#define AT_P2     25344                       // u64[1024] after the ring
#define AT_BYTES  (25344 * 4 + 1024 * 8)      // 109568 -> 2 blocks/SM

// ------------------------------------------------------------------
// 1) q[i] = dot(query, Wq[i]) + bq[i].  grid 128 x 256 (warp per row)
// ------------------------------------------------------------------
__global__ void k_qproj(const float* __restrict__ query,
                        const float* __restrict__ Wq,
                        const float* __restrict__ bq) {
    __shared__ __align__(16) float qs[DM];
    const int tid = threadIdx.x;
    for (int i = tid; i < DM; i += 256) qs[i] = query[i];
    __syncthreads();
    const int w = tid >> 5, lane = tid & 31;
    const int row = blockIdx.x * 8 + w;
    const float4* wr = (const float4*)(Wq + (size_t)row * DM);
    const float4* q4 = (const float4*)qs;
    float acc = 0.f;
#pragma unroll 8
    for (int k = lane; k < DM / 4; k += 32) {
        float4 a = wr[k], b = q4[k];
        acc += a.x * b.x + a.y * b.y + a.z * b.z + a.w * b.w;
    }
    acc = warp_red(acc);
    if (lane == 0) g_q[row] = acc + bq[row];
}

// ------------------------------------------------------------------
// 2) a[h][j] = sum_d q[h*64+d]*Wk[h*64+d][j];  c[h] = sum_d q*bk
//    grid 64 x 128, two launches (hofs 0/8) so k_attn is ncu idx 3.
// ------------------------------------------------------------------
__global__ void k_aprep(const float* __restrict__ Wk,
                        const float* __restrict__ bk, int hofs) {
    const int h = hofs + (blockIdx.x >> 3), sl = blockIdx.x & 7;
    const int tid = threadIdx.x;
    __shared__ float qh[DK];
    if (tid < DK) qh[tid] = g_q[h * DK + tid];
    __syncthreads();
    const int j = sl * 128 + tid;
    const float* base = Wk + (size_t)(h * DK) * DM + j;
    float acc = 0.f;
#pragma unroll 8
    for (int d = 0; d < DK; d++) acc += qh[d] * base[(size_t)d * DM];
    g_a[h * DM + j] = acc;
    if (sl == 0 && tid < 32) {
        float c = 0.f;
        for (int d = tid; d < DK; d += 32) c += qh[d] * bk[h * DK + d];
        c = warp_red(c);
        if (tid == 0) g_c[h] = c;
    }
}

// ------------------------------------------------------------------
// 3) FUSED attention (round-6 structure + 4-stage phase-A pipeline).
//    Phase A: scores -> exp -> p2 in SMEM. Key + a tiles streamed
//    through a 4-deep cp.async ring; ONE barrier per tile; lookahead
//    3 tiles (~900 cyc) covers DRAM latency.
//    Phase B: wpart = sum p*value, direct LDG MLP-8 (r6 verbatim).
// ------------------------------------------------------------------
__global__ void __launch_bounds__(256, 2) k_attn(const float* __restrict__ key,
                                                 const float* __restrict__ value) {
    extern __shared__ __align__(16) float smem[];
    u64* p2 = (u64*)(smem + AT_P2);

    const int tid = threadIdx.x;
    const int w = tid >> 5, lane = tid & 31;
    const int n0 = blockIdx.x * 64;

    const uint32_t smem_u32 = (uint32_t)__cvta_generic_to_shared(smem);

    // staging maps (r6): key 32x128 fl, a 16x128 fl per tile
    const int kr  = tid >> 3;            // key row 0..31
    const int kc4 = tid & 7;             // key f4 col base
    const int ah  = tid >> 4;            // a head 0..15
    const int ac  = tid & 15;            // a f4 col base
    const float4* ga4 = (const float4*)g_a;

#define AT_ISSUE(st, tt, krowp)                                                 \
    do {                                                                        \
        const uint32_t dk = smem_u32 + AT_KT(st) * 4;                           \
        const uint32_t da = smem_u32 + AT_AT(st) * 4;                           \
        _Pragma("unroll")                                                       \
        for (int k = 0; k < 4; k++) {                                           \
            const int c4 = kc4 + 8 * k;                                         \
            cp_async16(dk + (kr * 132 + c4 * 4) * 4, (krowp) + (tt) * 128 + c4 * 4); \
        }                                                                       \
        _Pragma("unroll")                                                       \
        for (int k = 0; k < 2; k++) {                                           \
            const int c4 = ac + 16 * k;                                         \
            cp_async16(da + (ah * 132 + c4 * 4) * 4, ga4 + ah * 256 + (tt) * 32 + c4); \
        }                                                                       \
        CP_COMMIT();                                                            \
    } while (0)

    // ---------------- Phase A ----------------
#pragma unroll 1
    for (int sub = 0; sub < 2; sub++) {
        const int n0s = n0 + sub * 32;
        const float* krow = key + (size_t)(n0s + kr) * DM;

        AT_ISSUE(0, 0, krow);
        AT_ISSUE(1, 1, krow);
        AT_ISSUE(2, 2, krow);

        ulonglong2 acc2[16];
#pragma unroll
        for (int h = 0; h < 16; h++) acc2[h] = make_ulonglong2(0ull, 0ull);

#pragma unroll
        for (int t = 0; t < 8; t++) {
            if (t == 7)      { CP_WAIT(0); }
            else if (t == 6) { CP_WAIT(1); }
            else             { CP_WAIT(2); }
            __syncthreads();
            const float* ktb = smem + AT_KT(t & 3);
            const float* atb = smem + AT_AT(t & 3);
#pragma unroll
            for (int q = 0; q < 4; q++) {
                const int j = w * 16 + q * 4;
                const ulonglong2 kv = *(const ulonglong2*)&ktb[lane * 132 + j];
#pragma unroll
                for (int h = 0; h < 16; h++) {
                    const ulonglong2 av = *(const ulonglong2*)&atb[h * 132 + j];
                    acc2[h].x = fma2(kv.x, av.x, acc2[h].x);
                    acc2[h].y = fma2(kv.y, av.y, acc2[h].y);
                }
            }
            if (t < 5) AT_ISSUE((t + 3) & 3, t + 3, krow);
        }

        // epilogue: cross-warp reduction (stage-0 region as scratch; drained)
        __syncthreads();
        float* red = smem + AT_KT(0);        // 4096 fl needed <= 4224
#pragma unroll
        for (int h = 0; h < 16; h++)
            red[h * 256 + w * 32 + lane] = sum2(acc2[h].x) + sum2(acc2[h].y);
        __syncthreads();
        const int h0 = tid >> 5;
        const int r  = tid & 31;
#pragma unroll
        for (int s = 0; s < 2; s++) {
            const int hh = h0 + 8 * s;
            float v = g_c[hh];
#pragma unroll
            for (int ww = 0; ww < 8; ww++) v += red[hh * 256 + ww * 32 + r];
            const float e = __expf(v);
            const unsigned b = __float_as_uint(e);
            p2[hh * 64 + sub * 32 + r] = ((u64)b << 32) | b;
            float z = warp_red(e);
            if (r == 0) g_Zpart[hh * 512 + blockIdx.x * 2 + sub] = z;
        }
        __syncthreads();   // red reads done before next sub refills stage 0
    }
#undef AT_ISSUE

    // ---------------- Phase B: p * value -> wpart (r6 verbatim) ----------------
    ulonglong2 acc[H];
#pragma unroll
    for (int h = 0; h < H; h++) acc[h] = make_ulonglong2(0ull, 0ull);

    const ulonglong2* vp = (const ulonglong2*)value + (size_t)n0 * 256 + tid;

    for (int nb = 0; nb < 64; nb += 8) {
        ulonglong2 v0 = vp[(size_t)(nb + 0) * 256];
        ulonglong2 v1 = vp[(size_t)(nb + 1) * 256];
        ulonglong2 v2 = vp[(size_t)(nb + 2) * 256];
        ulonglong2 v3 = vp[(size_t)(nb + 3) * 256];
        ulonglong2 v4 = vp[(size_t)(nb + 4) * 256];
        ulonglong2 v5 = vp[(size_t)(nb + 5) * 256];
        ulonglong2 v6 = vp[(size_t)(nb + 6) * 256];
        ulonglong2 v7 = vp[(size_t)(nb + 7) * 256];
#pragma unroll
        for (int h = 0; h < H; h++) {
            const u64* ph = &p2[h * 64 + nb];
            const ulonglong2 pA = *(const ulonglong2*)(ph + 0);
            const ulonglong2 pB = *(const ulonglong2*)(ph + 2);
            const ulonglong2 pC = *(const ulonglong2*)(ph + 4);
            const ulonglong2 pD = *(const ulonglong2*)(ph + 6);
            acc[h].x = fma2(pA.x, v0.x, acc[h].x); acc[h].y = fma2(pA.x, v0.y, acc[h].y);
            acc[h].x = fma2(pA.y, v1.x, acc[h].x); acc[h].y = fma2(pA.y, v1.y, acc[h].y);
            acc[h].x = fma2(pB.x, v2.x, acc[h].x); acc[h].y = fma2(pB.x, v2.y, acc[h].y);
            acc[h].x = fma2(pB.y, v3.x, acc[h].x); acc[h].y = fma2(pB.y, v3.y, acc[h].y);
            acc[h].x = fma2(pC.x, v4.x, acc[h].x); acc[h].y = fma2(pC.x, v4.y, acc[h].y);
            acc[h].x = fma2(pC.y, v5.x, acc[h].x); acc[h].y = fma2(pC.y, v5.y, acc[h].y);
            acc[h].x = fma2(pD.x, v6.x, acc[h].x); acc[h].y = fma2(pD.x, v6.y, acc[h].y);
            acc[h].x = fma2(pD.y, v7.x, acc[h].x); acc[h].y = fma2(pD.y, v7.y, acc[h].y);
        }
    }
    ulonglong2* wp = (ulonglong2*)&g_wpart[blockIdx.x][0];
#pragma unroll
    for (int h = 0; h < H; h++) wp[h * 256 + tid] = acc[h];
}

// ------------------------------------------------------------------
// 4) w[i] = (sum_c wpart[c][i]) / Z[h].  grid 256 x 256 (r6 version).
// ------------------------------------------------------------------
__global__ void k_wreduce() {
    __shared__ __align__(16) float4 part[256];
    __shared__ float zs;
    const int tid = threadIdx.x;
    const int cseg = tid >> 4;
    const int col  = tid & 15;
    const int b = blockIdx.x;
    const int h = b >> 4;
    const int f4col = b * 16 + col;

    const float4* wp4 = (const float4*)&g_wpart[0][0];
    float4 acc = make_float4(0.f, 0.f, 0.f, 0.f);
#pragma unroll
    for (int k = 0; k < 16; k++) {
        const float4 v = wp4[(size_t)(cseg * 16 + k) * 4096 + f4col];
        acc.x += v.x; acc.y += v.y; acc.z += v.z; acc.w += v.w;
    }
    part[tid] = acc;

    if (tid < 32) {
        const float4* zp = (const float4*)(g_Zpart + h * 512);
        float z = 0.f;
#pragma unroll
        for (int k = 0; k < 4; k++) {
            const float4 v = zp[tid * 4 + k];
            z += v.x + v.y + v.z + v.w;
        }
        z = warp_red(z);
        if (tid == 0) zs = z;
    }
    __syncthreads();

    if (tid < 16) {
        float4 s = part[tid];
#pragma unroll
        for (int k = 1; k < 16; k++) {
            const float4 v = part[k * 16 + tid];
            s.x += v.x; s.y += v.y; s.z += v.z; s.w += v.w;
        }
        const float inv = 1.0f / zs;
        s.x *= inv; s.y *= inv; s.z *= inv; s.w *= inv;
        ((float4*)g_w)[b * 16 + tid] = s;
    }
}

// ------------------------------------------------------------------
// 5) x[i] = dot(w[h], Wv[i]) + bv[i], h = i/64.  grid 128 x 256.
// ------------------------------------------------------------------
__global__ void k_xproj(const float* __restrict__ Wv,
                        const float* __restrict__ bv) {
    __shared__ __align__(16) float ws[DM];
    const int tid = threadIdx.x;
    const int h = blockIdx.x >> 3;
    for (int i = tid; i < DM; i += 256) ws[i] = g_w[h * DM + i];
    __syncthreads();
    const int w = tid >> 5, lane = tid & 31;
    const int row = blockIdx.x * 8 + w;
    const float4* wr = (const float4*)(Wv + (size_t)row * DM);
    const float4* q4 = (const float4*)ws;
    float acc = 0.f;
#pragma unroll 8
    for (int k = lane; k < DM / 4; k += 32) {
        float4 a = wr[k], b = q4[k];
        acc += a.x * b.x + a.y * b.y + a.z * b.z + a.w * b.w;
    }
    acc = warp_red(acc);
    if (lane == 0) g_x[row] = acc + bv[row];
}

// ------------------------------------------------------------------
// 6) out[i] = dot(x, Wo[i]) + bo[i].  grid 128 x 256.
// ------------------------------------------------------------------
__global__ void k_out(const float* __restrict__ Wo,
                      const float* __restrict__ bo,
                      float* __restrict__ out) {
    __shared__ __align__(16) float xs[DM];
    const int tid = threadIdx.x;
    for (int i = tid; i < DM; i += 256) xs[i] = g_x[i];
    __syncthreads();
    const int w = tid >> 5, lane = tid & 31;
    const int row = blockIdx.x * 8 + w;
    const float4* wr = (const float4*)(Wo + (size_t)row * DM);
    const float4* q4 = (const float4*)xs;
    float acc = 0.f;
#pragma unroll 8
    for (int k = lane; k < DM / 4; k += 32) {
        float4 a = wr[k], b = q4[k];
        acc += a.x * b.x + a.y * b.y + a.z * b.z + a.w * b.w;
    }
    acc = warp_red(acc);
    if (lane == 0) out[row] = acc + bo[row];
}

// ------------------------------------------------------------------
extern "C" void kernel_launch(void* const* d_in, const int* in_sizes, int n_in,
                              void* d_out, int out_size) {
    (void)in_sizes; (void)n_in; (void)out_size;
    const float* query = (const float*)d_in[0];
    const float* key   = (const float*)d_in[1];
    const float* value = (const float*)d_in[2];
    const float* Wq    = (const float*)d_in[3];
    const float* bq    = (const float*)d_in[4];
    const float* Wk    = (const float*)d_in[5];
    const float* bk    = (const float*)d_in[6];
    const float* Wv    = (const float*)d_in[7];
    const float* bv    = (const float*)d_in[8];
    const float* Wo    = (const float*)d_in[9];
    const float* bo    = (const float*)d_in[10];
    float* out = (float*)d_out;

    cudaFuncSetAttribute(k_attn, cudaFuncAttributeMaxDynamicSharedMemorySize,
                         AT_BYTES);

    k_qproj  <<<128, 256>>>(query, Wq, bq);           // idx 0
    k_aprep  <<<64, 128>>>(Wk, bk, 0);                // idx 1
    k_aprep  <<<64, 128>>>(Wk, bk, 8);                // idx 2
    k_attn   <<<NCHUNK, 256, AT_BYTES>>>(key, value); // idx 3  <- ncu window
    k_wreduce<<<256, 256>>>();                        // idx 4
    k_xproj  <<<128, 256>>>(Wv, bv);                  // idx 5
    k_out    <<<128, 256>>>(Wo, bo, out);             // idx 6
}

// round 13
// speedup vs baseline: 1.1489x; 1.0216x over previous
#include <cuda_runtime.h>
#include <math.h>
#include <stdint.h>

#define H       16
#define DM      1024
#define DK      64
#define NW      16384
#define NCHUNK  256     // attn blocks; 64 rows each

typedef unsigned long long u64;

// ---- scratch (static __device__ arrays; no allocation) ----
__device__ __align__(16) float g_a[H * DM];
__device__ __align__(16) float g_c[H];
__device__ __align__(16) float g_Zpart[H * 512];
__device__ __align__(16) float g_wpart[NCHUNK][H * DM];
__device__ __align__(16) float g_w[H * DM];
__device__ __align__(16) float g_x[DM];

__device__ __forceinline__ float warp_red(float v) {
#pragma unroll
    for (int o = 16; o; o >>= 1) v += __shfl_down_sync(0xffffffffu, v, o);
    return v;
}

// packed f32x2 FMA (Blackwell)
__device__ __forceinline__ u64 fma2(u64 a, u64 b, u64 c) {
    u64 d;
    asm("fma.rn.f32x2 %0, %1, %2, %3;" : "=l"(d) : "l"(a), "l"(b), "l"(c));
    return d;
}
__device__ __forceinline__ float sum2(u64 v) {
    return __uint_as_float((unsigned)v) + __uint_as_float((unsigned)(v >> 32));
}

// cp.async helpers
__device__ __forceinline__ void cp_async16(uint32_t smem_addr, const void* gptr) {
    asm volatile("cp.async.cg.shared.global [%0], [%1], 16;"
                 :: "r"(smem_addr), "l"(gptr));
}
#define CP_COMMIT()  asm volatile("cp.async.commit_group;")
#define CP_WAIT(n)   asm volatile("cp.async.wait_group %0;" :: "n"(n))

// k_attn dynamic SMEM layout (floats) — round-6 champion layout:
//   a_s : [0, 16384)                 16 x 1024, no pad (broadcast reads)
//   kt0 : [16384, +4224)             32 x 132 padded key tile
//   kt1 : [20608, +4224)
//   p2  : u64[1024] (8 KB)
#define SM_A    0
#define SM_KT0  16384
#define SM_KT1  (16384 + 4224)
#define SM_P2   (16384 + 8448)
#define SM_BYTES ((16384 + 8448) * 4 + 1024 * 8)   // 107520

// ------------------------------------------------------------------
// 1) k_prep: fused q-projection + a/c prep.  grid 32 x 256.
//    Block (h, jh): computes q rows [h*64, h*64+64) (redundant across
//    the 2 j-halves), then a[h][jh*512 .. +512) and c[h] (jh==0).
// ------------------------------------------------------------------
__global__ void k_prep(const float* __restrict__ query,
                       const float* __restrict__ Wq,
                       const float* __restrict__ bq,
                       const float* __restrict__ Wk,
                       const float* __restrict__ bk) {
    __shared__ __align__(16) float qs[DM];
    __shared__ float qh_s[DK];
    const int tid = threadIdx.x;
    const int h = blockIdx.x >> 1, jh = blockIdx.x & 1;
    const int w = tid >> 5, lane = tid & 31;

    for (int i = tid; i < DM; i += 256) qs[i] = query[i];
    __syncthreads();

    // 64 q-rows for this head: warp per row, 8 rounds
    const float4* q4 = (const float4*)qs;
#pragma unroll 1
    for (int r = 0; r < 8; r++) {
        const int row = h * DK + r * 8 + w;
        const float4* wr = (const float4*)(Wq + (size_t)row * DM);
        float acc = 0.f;
#pragma unroll 8
        for (int k = lane; k < DM / 4; k += 32) {
            float4 a = wr[k], b = q4[k];
            acc += a.x * b.x + a.y * b.y + a.z * b.z + a.w * b.w;
        }
        acc = warp_red(acc);
        if (lane == 0) qh_s[r * 8 + w] = acc + bq[row];
    }
    __syncthreads();

    // a[h][j] for this half: 2 adjacent cols per thread (float2 loads)
    const int j = jh * 512 + tid * 2;
    const float2* base = (const float2*)(Wk + (size_t)(h * DK) * DM + j);
    float a0 = 0.f, a1 = 0.f;
#pragma unroll 8
    for (int d = 0; d < DK; d++) {
        const float qv = qh_s[d];
        const float2 v = base[(size_t)d * (DM / 2)];
        a0 += qv * v.x;
        a1 += qv * v.y;
    }
    g_a[h * DM + j]     = a0;
    g_a[h * DM + j + 1] = a1;

    if (jh == 0 && tid < 32) {
        float c = 0.f;
        for (int d = tid; d < DK; d += 32) c += qh_s[d] * bk[h * DK + d];
        c = warp_red(c);
        if (tid == 0) g_c[h] = c;
    }
}

// ------------------------------------------------------------------
// 2) FUSED attention — round-6 champion, verbatim.
//    Phase A: a resident in SMEM; key tiles double-buffered via
//    cp.async (1-tile lookahead, zero register cost).
//    Phase B: wpart = sum p*value, direct LDG MLP-8.
// ------------------------------------------------------------------
__global__ void __launch_bounds__(256, 2) k_attn(const float* __restrict__ key,
                                                 const float* __restrict__ value) {
    extern __shared__ __align__(16) float smem[];
    float* a_s = smem + SM_A;
    u64*   p2  = (u64*)(smem + SM_P2);

    const int tid = threadIdx.x;
    const int w = tid >> 5, lane = tid & 31;
    const int n0 = blockIdx.x * 64;

    const uint32_t smem_u32 = (uint32_t)__cvta_generic_to_shared(smem);
    const uint32_t a_addr   = smem_u32 + SM_A * 4;
    const uint32_t kt_addr[2] = { smem_u32 + SM_KT0 * 4, smem_u32 + SM_KT1 * 4 };

    const int r_ld = tid >> 3;   // key stage: row (0..31)
    const int c4b  = tid & 7;    // key stage: f4 col base

    // ---- prologue: a (once) ----
#pragma unroll
    for (int k = 0; k < 16; k++) {
        const int f4 = tid + 256 * k;
        cp_async16(a_addr + f4 * 16, (const float4*)g_a + f4);
    }
    CP_COMMIT();

    // ---------------- Phase A ----------------
#pragma unroll 1
    for (int sub = 0; sub < 2; sub++) {
        const int n0s = n0 + sub * 32;
        const float* krow = key + (size_t)(n0s + r_ld) * DM;

        // issue tiles 0 and 1
#pragma unroll
        for (int k = 0; k < 4; k++) {
            const int c4 = c4b + 8 * k;
            cp_async16(kt_addr[0] + (r_ld * 132 + c4 * 4) * 4, krow + c4 * 4);
        }
        CP_COMMIT();
#pragma unroll
        for (int k = 0; k < 4; k++) {
            const int c4 = c4b + 8 * k;
            cp_async16(kt_addr[1] + (r_ld * 132 + c4 * 4) * 4, krow + 128 + c4 * 4);
        }
        CP_COMMIT();

        ulonglong2 acc2[16];
#pragma unroll
        for (int h = 0; h < 16; h++) acc2[h] = make_ulonglong2(0ull, 0ull);

#pragma unroll
        for (int t = 0; t < 8; t++) {
            if (t == 7) { CP_WAIT(0); } else { CP_WAIT(1); }
            __syncthreads();
            const float* ktb = smem + ((t & 1) ? SM_KT1 : SM_KT0);
#pragma unroll
            for (int q = 0; q < 4; q++) {
                const int j = w * 16 + q * 4;
                const ulonglong2 kv = *(const ulonglong2*)&ktb[lane * 132 + j];
#pragma unroll
                for (int h = 0; h < 16; h++) {
                    const ulonglong2 av = *(const ulonglong2*)&a_s[h * 1024 + t * 128 + j];
                    acc2[h].x = fma2(kv.x, av.x, acc2[h].x);
                    acc2[h].y = fma2(kv.y, av.y, acc2[h].y);
                }
            }
            __syncthreads();
            if (t < 6) {
                const uint32_t dst = kt_addr[t & 1];
#pragma unroll
                for (int k = 0; k < 4; k++) {
                    const int c4 = c4b + 8 * k;
                    cp_async16(dst + (r_ld * 132 + c4 * 4) * 4,
                               krow + (t + 2) * 128 + c4 * 4);
                }
                CP_COMMIT();
            }
        }

        // cross-warp reduction (kt0 free after drain)
        float* red = smem + SM_KT0;
#pragma unroll
        for (int h = 0; h < 16; h++)
            red[h * 256 + w * 32 + lane] = sum2(acc2[h].x) + sum2(acc2[h].y);
        __syncthreads();
        const int h0 = tid >> 5;
        const int r  = tid & 31;
#pragma unroll
        for (int s = 0; s < 2; s++) {
            const int hh = h0 + 8 * s;
            float v = g_c[hh];
#pragma unroll
            for (int ww = 0; ww < 8; ww++) v += red[hh * 256 + ww * 32 + r];
            const float e = __expf(v);
            const unsigned b = __float_as_uint(e);
            p2[hh * 64 + sub * 32 + r] = ((u64)b << 32) | b;
            float z = warp_red(e);
            if (r == 0) g_Zpart[hh * 512 + blockIdx.x * 2 + sub] = z;
        }
        __syncthreads();   // red reads done before sub1 re-issues into kt0
    }

    // ---------------- Phase B: p * value -> wpart ----------------
    ulonglong2 acc[H];
#pragma unroll
    for (int h = 0; h < H; h++) acc[h] = make_ulonglong2(0ull, 0ull);

    const ulonglong2* vp = (const ulonglong2*)value + (size_t)n0 * 256 + tid;

    for (int nb = 0; nb < 64; nb += 8) {
        ulonglong2 v0 = vp[(size_t)(nb + 0) * 256];
        ulonglong2 v1 = vp[(size_t)(nb + 1) * 256];
        ulonglong2 v2 = vp[(size_t)(nb + 2) * 256];
        ulonglong2 v3 = vp[(size_t)(nb + 3) * 256];
        ulonglong2 v4 = vp[(size_t)(nb + 4) * 256];
        ulonglong2 v5 = vp[(size_t)(nb + 5) * 256];
        ulonglong2 v6 = vp[(size_t)(nb + 6) * 256];
        ulonglong2 v7 = vp[(size_t)(nb + 7) * 256];
#pragma unroll
        for (int h = 0; h < H; h++) {
            const u64* ph = &p2[h * 64 + nb];
            const ulonglong2 pA = *(const ulonglong2*)(ph + 0);
            const ulonglong2 pB = *(const ulonglong2*)(ph + 2);
            const ulonglong2 pC = *(const ulonglong2*)(ph + 4);
            const ulonglong2 pD = *(const ulonglong2*)(ph + 6);
            acc[h].x = fma2(pA.x, v0.x, acc[h].x); acc[h].y = fma2(pA.x, v0.y, acc[h].y);
            acc[h].x = fma2(pA.y, v1.x, acc[h].x); acc[h].y = fma2(pA.y, v1.y, acc[h].y);
            acc[h].x = fma2(pB.x, v2.x, acc[h].x); acc[h].y = fma2(pB.x, v2.y, acc[h].y);
            acc[h].x = fma2(pB.y, v3.x, acc[h].x); acc[h].y = fma2(pB.y, v3.y, acc[h].y);
            acc[h].x = fma2(pC.x, v4.x, acc[h].x); acc[h].y = fma2(pC.x, v4.y, acc[h].y);
            acc[h].x = fma2(pC.y, v5.x, acc[h].x); acc[h].y = fma2(pC.y, v5.y, acc[h].y);
            acc[h].x = fma2(pD.x, v6.x, acc[h].x); acc[h].y = fma2(pD.x, v6.y, acc[h].y);
            acc[h].x = fma2(pD.y, v7.x, acc[h].x); acc[h].y = fma2(pD.y, v7.y, acc[h].y);
        }
    }
    ulonglong2* wp = (ulonglong2*)&g_wpart[blockIdx.x][0];
#pragma unroll
    for (int h = 0; h < H; h++) wp[h * 256 + tid] = acc[h];
}

// ------------------------------------------------------------------
// 3) w[i] = (sum_c wpart[c][i]) / Z[h].  grid 1024 x 128.
//    Block covers 4 f4-cols (one head); 32 threads x 8 chunks per col.
// ------------------------------------------------------------------
__global__ void k_wreduce() {
    __shared__ __align__(16) float4 part[128];
    __shared__ float zs;
    const int tid = threadIdx.x;
    const int fl   = tid & 3;                 // f4 col within block
    const int cseg = tid >> 2;                // 0..31 (8 chunks each)
    const int b = blockIdx.x;
    const int h = b >> 6;                     // 64 blocks per head
    const int f4col = b * 4 + fl;

    const float4* wp4 = (const float4*)&g_wpart[0][0];
    float4 acc = make_float4(0.f, 0.f, 0.f, 0.f);
#pragma unroll
    for (int k = 0; k < 8; k++) {
        const float4 v = wp4[(size_t)(cseg * 8 + k) * 4096 + f4col];
        acc.x += v.x; acc.y += v.y; acc.z += v.z; acc.w += v.w;
    }
    part[tid] = acc;

    if (tid < 32) {
        const float4* zp = (const float4*)(g_Zpart + h * 512);
        float z = 0.f;
#pragma unroll
        for (int k = 0; k < 4; k++) {
            const float4 v = zp[tid * 4 + k];
            z += v.x + v.y + v.z + v.w;
        }
        z = warp_red(z);
        if (tid == 0) zs = z;
    }
    __syncthreads();

    if (tid < 4) {
        float4 s = part[tid];
#pragma unroll
        for (int g = 1; g < 32; g++) {
            const float4 v = part[g * 4 + tid];
            s.x += v.x; s.y += v.y; s.z += v.z; s.w += v.w;
        }
        const float inv = 1.0f / zs;
        s.x *= inv; s.y *= inv; s.z *= inv; s.w *= inv;
        ((float4*)g_w)[b * 4 + tid] = s;
    }
}

// ------------------------------------------------------------------
// 4) x[i] = dot(w[h], Wv[i]) + bv[i], h = i/64.  grid 256 x 128.
// ------------------------------------------------------------------
__global__ void k_xproj(const float* __restrict__ Wv,
                        const float* __restrict__ bv) {
    __shared__ __align__(16) float ws[DM];
    const int tid = threadIdx.x;
    const int h = blockIdx.x >> 4;            // 4 rows/block, 16 blocks/head
    for (int i = tid; i < DM; i += 128) ws[i] = g_w[h * DM + i];
    __syncthreads();
    const int w = tid >> 5, lane = tid & 31;
    const int row = blockIdx.x * 4 + w;
    const float4* wr = (const float4*)(Wv + (size_t)row * DM);
    const float4* q4 = (const float4*)ws;
    float acc = 0.f;
#pragma unroll 8
    for (int k = lane; k < DM / 4; k += 32) {
        float4 a = wr[k], b = q4[k];
        acc += a.x * b.x + a.y * b.y + a.z * b.z + a.w * b.w;
    }
    acc = warp_red(acc);
    if (lane == 0) g_x[row] = acc + bv[row];
}

// ------------------------------------------------------------------
// 5) out[i] = dot(x, Wo[i]) + bo[i].  grid 256 x 128.
// ------------------------------------------------------------------
__global__ void k_out(const float* __restrict__ Wo,
                      const float* __restrict__ bo,
                      float* __restrict__ out) {
    __shared__ __align__(16) float xs[DM];
    const int tid = threadIdx.x;
    for (int i = tid; i < DM; i += 128) xs[i] = g_x[i];
    __syncthreads();
    const int w = tid >> 5, lane = tid & 31;
    const int row = blockIdx.x * 4 + w;
    const float4* wr = (const float4*)(Wo + (size_t)row * DM);
    const float4* q4 = (const float4*)xs;
    float acc = 0.f;
#pragma unroll 8
    for (int k = lane; k < DM / 4; k += 32) {
        float4 a = wr[k], b = q4[k];
        acc += a.x * b.x + a.y * b.y + a.z * b.z + a.w * b.w;
    }
    acc = warp_red(acc);
    if (lane == 0) out[row] = acc + bo[row];
}

// ------------------------------------------------------------------
extern "C" void kernel_launch(void* const* d_in, const int* in_sizes, int n_in,
                              void* d_out, int out_size) {
    (void)in_sizes; (void)n_in; (void)out_size;
    const float* query = (const float*)d_in[0];
    const float* key   = (const float*)d_in[1];
    const float* value = (const float*)d_in[2];
    const float* Wq    = (const float*)d_in[3];
    const float* bq    = (const float*)d_in[4];
    const float* Wk    = (const float*)d_in[5];
    const float* bk    = (const float*)d_in[6];
    const float* Wv    = (const float*)d_in[7];
    const float* bv    = (const float*)d_in[8];
    const float* Wo    = (const float*)d_in[9];
    const float* bo    = (const float*)d_in[10];
    float* out = (float*)d_out;

    cudaFuncSetAttribute(k_attn, cudaFuncAttributeMaxDynamicSharedMemorySize,
                         SM_BYTES);

    k_prep   <<<32, 256>>>(query, Wq, bq, Wk, bk);    // idx 0
    k_attn   <<<NCHUNK, 256, SM_BYTES>>>(key, value); // idx 1
    k_wreduce<<<1024, 128>>>();                       // idx 2
    k_xproj  <<<256, 128>>>(Wv, bv);                  // idx 3  <- ncu window
    k_out    <<<256, 128>>>(Wo, bo, out);             // idx 4
}

// round 14
// speedup vs baseline: 1.3915x; 1.2111x over previous
#include <cuda_runtime.h>
#include <math.h>
#include <stdint.h>

#define H       16
#define DM      1024
#define DK      64
#define NW      16384
#define NCHUNK  256     // attn blocks; 64 rows each

typedef unsigned long long u64;

// ---- scratch (static __device__ arrays; no allocation) ----
__device__ __align__(16) float g_q[DM];
__device__ __align__(16) float g_a[H * DM];
__device__ __align__(16) float g_c[H];
__device__ __align__(16) float g_Zpart[H * 512];
__device__ __align__(16) float g_wpart[NCHUNK][H * DM];
__device__ __align__(16) float g_w[H * DM];
__device__ __align__(16) float g_x[DM];

__device__ __forceinline__ float warp_red(float v) {
#pragma unroll
    for (int o = 16; o; o >>= 1) v += __shfl_down_sync(0xffffffffu, v, o);
    return v;
}

// packed f32x2 FMA (Blackwell)
__device__ __forceinline__ u64 fma2(u64 a, u64 b, u64 c) {
    u64 d;
    asm("fma.rn.f32x2 %0, %1, %2, %3;" : "=l"(d) : "l"(a), "l"(b), "l"(c));
    return d;
}
__device__ __forceinline__ float sum2(u64 v) {
    return __uint_as_float((unsigned)v) + __uint_as_float((unsigned)(v >> 32));
}

// cp.async helpers
__device__ __forceinline__ void cp_async16(uint32_t smem_addr, const void* gptr) {
    asm volatile("cp.async.cg.shared.global [%0], [%1], 16;"
                 :: "r"(smem_addr), "l"(gptr));
}
#define CP_COMMIT()  asm volatile("cp.async.commit_group;")
#define CP_WAIT(n)   asm volatile("cp.async.wait_group %0;" :: "n"(n))

// k_attn dynamic SMEM layout (floats) — round-6 champion layout:
#define SM_A    0
#define SM_KT0  16384
#define SM_KT1  (16384 + 4224)
#define SM_P2   (16384 + 8448)
#define SM_BYTES ((16384 + 8448) * 4 + 1024 * 8)   // 107520

// ------------------------------------------------------------------
// 1) q[i] = dot(query, Wq[i]) + bq[i].  grid 128 x 256 (r6 verbatim)
// ------------------------------------------------------------------
__global__ void k_qproj(const float* __restrict__ query,
                        const float* __restrict__ Wq,
                        const float* __restrict__ bq) {
    __shared__ __align__(16) float qs[DM];
    const int tid = threadIdx.x;
    for (int i = tid; i < DM; i += 256) qs[i] = query[i];
    __syncthreads();
    const int w = tid >> 5, lane = tid & 31;
    const int row = blockIdx.x * 8 + w;
    const float4* wr = (const float4*)(Wq + (size_t)row * DM);
    const float4* q4 = (const float4*)qs;
    float acc = 0.f;
#pragma unroll 8
    for (int k = lane; k < DM / 4; k += 32) {
        float4 a = wr[k], b = q4[k];
        acc += a.x * b.x + a.y * b.y + a.z * b.z + a.w * b.w;
    }
    acc = warp_red(acc);
    if (lane == 0) g_q[row] = acc + bq[row];
}

// ------------------------------------------------------------------
// 2) a[h][j] = sum_d q[h*64+d]*Wk[h*64+d][j];  c[h] (r6 verbatim)
// ------------------------------------------------------------------
__global__ void k_aprep(const float* __restrict__ Wk,
                        const float* __restrict__ bk) {
    const int h = blockIdx.x >> 3, sl = blockIdx.x & 7;
    const int tid = threadIdx.x;
    __shared__ float qh[DK];
    if (tid < DK) qh[tid] = g_q[h * DK + tid];
    __syncthreads();
    const int j = sl * 128 + tid;
    const float* base = Wk + (size_t)(h * DK) * DM + j;
    float acc = 0.f;
#pragma unroll 8
    for (int d = 0; d < DK; d++) acc += qh[d] * base[(size_t)d * DM];
    g_a[h * DM + j] = acc;
    if (sl == 0 && tid < 32) {
        float c = 0.f;
        for (int d = tid; d < DK; d += 32) c += qh[d] * bk[h * DK + d];
        c = warp_red(c);
        if (tid == 0) g_c[h] = c;
    }
}

// ------------------------------------------------------------------
// 3) FUSED attention — round-6 champion, verbatim.
// ------------------------------------------------------------------
__global__ void __launch_bounds__(256, 2) k_attn(const float* __restrict__ key,
                                                 const float* __restrict__ value) {
    extern __shared__ __align__(16) float smem[];
    float* a_s = smem + SM_A;
    u64*   p2  = (u64*)(smem + SM_P2);

    const int tid = threadIdx.x;
    const int w = tid >> 5, lane = tid & 31;
    const int n0 = blockIdx.x * 64;

    const uint32_t smem_u32 = (uint32_t)__cvta_generic_to_shared(smem);
    const uint32_t a_addr   = smem_u32 + SM_A * 4;
    const uint32_t kt_addr[2] = { smem_u32 + SM_KT0 * 4, smem_u32 + SM_KT1 * 4 };

    const int r_ld = tid >> 3;   // key stage: row (0..31)
    const int c4b  = tid & 7;    // key stage: f4 col base

    // ---- prologue: a (once) ----
#pragma unroll
    for (int k = 0; k < 16; k++) {
        const int f4 = tid + 256 * k;
        cp_async16(a_addr + f4 * 16, (const float4*)g_a + f4);
    }
    CP_COMMIT();

    // ---------------- Phase A ----------------
#pragma unroll 1
    for (int sub = 0; sub < 2; sub++) {
        const int n0s = n0 + sub * 32;
        const float* krow = key + (size_t)(n0s + r_ld) * DM;

#pragma unroll
        for (int k = 0; k < 4; k++) {
            const int c4 = c4b + 8 * k;
            cp_async16(kt_addr[0] + (r_ld * 132 + c4 * 4) * 4, krow + c4 * 4);
        }
        CP_COMMIT();
#pragma unroll
        for (int k = 0; k < 4; k++) {
            const int c4 = c4b + 8 * k;
            cp_async16(kt_addr[1] + (r_ld * 132 + c4 * 4) * 4, krow + 128 + c4 * 4);
        }
        CP_COMMIT();

        ulonglong2 acc2[16];
#pragma unroll
        for (int h = 0; h < 16; h++) acc2[h] = make_ulonglong2(0ull, 0ull);

#pragma unroll
        for (int t = 0; t < 8; t++) {
            if (t == 7) { CP_WAIT(0); } else { CP_WAIT(1); }
            __syncthreads();
            const float* ktb = smem + ((t & 1) ? SM_KT1 : SM_KT0);
#pragma unroll
            for (int q = 0; q < 4; q++) {
                const int j = w * 16 + q * 4;
                const ulonglong2 kv = *(const ulonglong2*)&ktb[lane * 132 + j];
#pragma unroll
                for (int h = 0; h < 16; h++) {
                    const ulonglong2 av = *(const ulonglong2*)&a_s[h * 1024 + t * 128 + j];
                    acc2[h].x = fma2(kv.x, av.x, acc2[h].x);
                    acc2[h].y = fma2(kv.y, av.y, acc2[h].y);
                }
            }
            __syncthreads();
            if (t < 6) {
                const uint32_t dst = kt_addr[t & 1];
#pragma unroll
                for (int k = 0; k < 4; k++) {
                    const int c4 = c4b + 8 * k;
                    cp_async16(dst + (r_ld * 132 + c4 * 4) * 4,
                               krow + (t + 2) * 128 + c4 * 4);
                }
                CP_COMMIT();
            }
        }

        float* red = smem + SM_KT0;
#pragma unroll
        for (int h = 0; h < 16; h++)
            red[h * 256 + w * 32 + lane] = sum2(acc2[h].x) + sum2(acc2[h].y);
        __syncthreads();
        const int h0 = tid >> 5;
        const int r  = tid & 31;
#pragma unroll
        for (int s = 0; s < 2; s++) {
            const int hh = h0 + 8 * s;
            float v = g_c[hh];
#pragma unroll
            for (int ww = 0; ww < 8; ww++) v += red[hh * 256 + ww * 32 + r];
            const float e = __expf(v);
            const unsigned b = __float_as_uint(e);
            p2[hh * 64 + sub * 32 + r] = ((u64)b << 32) | b;
            float z = warp_red(e);
            if (r == 0) g_Zpart[hh * 512 + blockIdx.x * 2 + sub] = z;
        }
        __syncthreads();
    }

    // ---------------- Phase B ----------------
    ulonglong2 acc[H];
#pragma unroll
    for (int h = 0; h < H; h++) acc[h] = make_ulonglong2(0ull, 0ull);

    const ulonglong2* vp = (const ulonglong2*)value + (size_t)n0 * 256 + tid;

    for (int nb = 0; nb < 64; nb += 8) {
        ulonglong2 v0 = vp[(size_t)(nb + 0) * 256];
        ulonglong2 v1 = vp[(size_t)(nb + 1) * 256];
        ulonglong2 v2 = vp[(size_t)(nb + 2) * 256];
        ulonglong2 v3 = vp[(size_t)(nb + 3) * 256];
        ulonglong2 v4 = vp[(size_t)(nb + 4) * 256];
        ulonglong2 v5 = vp[(size_t)(nb + 5) * 256];
        ulonglong2 v6 = vp[(size_t)(nb + 6) * 256];
        ulonglong2 v7 = vp[(size_t)(nb + 7) * 256];
#pragma unroll
        for (int h = 0; h < H; h++) {
            const u64* ph = &p2[h * 64 + nb];
            const ulonglong2 pA = *(const ulonglong2*)(ph + 0);
            const ulonglong2 pB = *(const ulonglong2*)(ph + 2);
            const ulonglong2 pC = *(const ulonglong2*)(ph + 4);
            const ulonglong2 pD = *(const ulonglong2*)(ph + 6);
            acc[h].x = fma2(pA.x, v0.x, acc[h].x); acc[h].y = fma2(pA.x, v0.y, acc[h].y);
            acc[h].x = fma2(pA.y, v1.x, acc[h].x); acc[h].y = fma2(pA.y, v1.y, acc[h].y);
            acc[h].x = fma2(pB.x, v2.x, acc[h].x); acc[h].y = fma2(pB.x, v2.y, acc[h].y);
            acc[h].x = fma2(pB.y, v3.x, acc[h].x); acc[h].y = fma2(pB.y, v3.y, acc[h].y);
            acc[h].x = fma2(pC.x, v4.x, acc[h].x); acc[h].y = fma2(pC.x, v4.y, acc[h].y);
            acc[h].x = fma2(pC.y, v5.x, acc[h].x); acc[h].y = fma2(pC.y, v5.y, acc[h].y);
            acc[h].x = fma2(pD.x, v6.x, acc[h].x); acc[h].y = fma2(pD.x, v6.y, acc[h].y);
            acc[h].x = fma2(pD.y, v7.x, acc[h].x); acc[h].y = fma2(pD.y, v7.y, acc[h].y);
        }
    }
    ulonglong2* wp = (ulonglong2*)&g_wpart[blockIdx.x][0];
#pragma unroll
    for (int h = 0; h < H; h++) wp[h * 256 + tid] = acc[h];
}

// ------------------------------------------------------------------
// 4) w[i] = (sum_c wpart[c][i]) / Z[h].  grid 1024 x 128 (wide).
// ------------------------------------------------------------------
__global__ void k_wreduce() {
    __shared__ __align__(16) float4 part[128];
    __shared__ float zs;
    const int tid = threadIdx.x;
    const int fl   = tid & 3;                 // f4 col within block
    const int cseg = tid >> 2;                // 0..31 (8 chunks each)
    const int b = blockIdx.x;
    const int h = b >> 6;                     // 64 blocks per head
    const int f4col = b * 4 + fl;

    const float4* wp4 = (const float4*)&g_wpart[0][0];
    float4 acc = make_float4(0.f, 0.f, 0.f, 0.f);
#pragma unroll
    for (int k = 0; k < 8; k++) {
        const float4 v = wp4[(size_t)(cseg * 8 + k) * 4096 + f4col];
        acc.x += v.x; acc.y += v.y; acc.z += v.z; acc.w += v.w;
    }
    part[tid] = acc;

    if (tid < 32) {
        const float4* zp = (const float4*)(g_Zpart + h * 512);
        float z = 0.f;
#pragma unroll
        for (int k = 0; k < 4; k++) {
            const float4 v = zp[tid * 4 + k];
            z += v.x + v.y + v.z + v.w;
        }
        z = warp_red(z);
        if (tid == 0) zs = z;
    }
    __syncthreads();

    if (tid < 4) {
        float4 s = part[tid];
#pragma unroll
        for (int g = 1; g < 32; g++) {
            const float4 v = part[g * 4 + tid];
            s.x += v.x; s.y += v.y; s.z += v.z; s.w += v.w;
        }
        const float inv = 1.0f / zs;
        s.x *= inv; s.y *= inv; s.z *= inv; s.w *= inv;
        ((float4*)g_w)[b * 4 + tid] = s;
    }
}

// ------------------------------------------------------------------
// 5) x[i] = dot(w[h], Wv[i]) + bv[i].  grid 512 x 256.
//    Block = 2 rows x 4 k-quarter warps; fixed-order partial combine.
// ------------------------------------------------------------------
__global__ void k_xproj(const float* __restrict__ Wv,
                        const float* __restrict__ bv) {
    __shared__ __align__(16) float ws[DM];
    __shared__ float part[8];
    const int tid = threadIdx.x;
    const int b = blockIdx.x;
    const int h = b >> 5;                    // rows b*2, b*2+1 share head
    ((float4*)ws)[tid] = ((const float4*)(g_w + h * DM))[tid];
    __syncthreads();
    const int w = tid >> 5, lane = tid & 31;
    const int row = b * 2 + (w >> 2);
    const int kq = w & 3;                    // k-quarter [kq*256, +256)
    const float4* wr = (const float4*)(Wv + (size_t)row * DM) + kq * 64;
    const float4* q4 = (const float4*)ws + kq * 64;
    float acc = 0.f;
#pragma unroll
    for (int k = lane; k < 64; k += 32) {
        float4 a = wr[k], bb = q4[k];
        acc += a.x * bb.x + a.y * bb.y + a.z * bb.z + a.w * bb.w;
    }
    acc = warp_red(acc);
    if (lane == 0) part[w] = acc;
    __syncthreads();
    if (tid < 2) {
        const int r = b * 2 + tid;
        const float s = part[tid * 4] + part[tid * 4 + 1]
                      + part[tid * 4 + 2] + part[tid * 4 + 3];
        g_x[r] = s + bv[r];
    }
}

// ------------------------------------------------------------------
// 6) out[i] = dot(x, Wo[i]) + bo[i].  grid 512 x 256 (same scheme).
// ------------------------------------------------------------------
__global__ void k_out(const float* __restrict__ Wo,
                      const float* __restrict__ bo,
                      float* __restrict__ out) {
    __shared__ __align__(16) float xs[DM];
    __shared__ float part[8];
    const int tid = threadIdx.x;
    const int b = blockIdx.x;
    ((float4*)xs)[tid] = ((const float4*)g_x)[tid];
    __syncthreads();
    const int w = tid >> 5, lane = tid & 31;
    const int row = b * 2 + (w >> 2);
    const int kq = w & 3;
    const float4* wr = (const float4*)(Wo + (size_t)row * DM) + kq * 64;
    const float4* q4 = (const float4*)xs + kq * 64;
    float acc = 0.f;
#pragma unroll
    for (int k = lane; k < 64; k += 32) {
        float4 a = wr[k], bb = q4[k];
        acc += a.x * bb.x + a.y * bb.y + a.z * bb.z + a.w * bb.w;
    }
    acc = warp_red(acc);
    if (lane == 0) part[w] = acc;
    __syncthreads();
    if (tid < 2) {
        const int r = b * 2 + tid;
        const float s = part[tid * 4] + part[tid * 4 + 1]
                      + part[tid * 4 + 2] + part[tid * 4 + 3];
        out[r] = s + bo[r];
    }
}

// ------------------------------------------------------------------
extern "C" void kernel_launch(void* const* d_in, const int* in_sizes, int n_in,
                              void* d_out, int out_size) {
    (void)in_sizes; (void)n_in; (void)out_size;
    const float* query = (const float*)d_in[0];
    const float* key   = (const float*)d_in[1];
    const float* value = (const float*)d_in[2];
    const float* Wq    = (const float*)d_in[3];
    const float* bq    = (const float*)d_in[4];
    const float* Wk    = (const float*)d_in[5];
    const float* bk    = (const float*)d_in[6];
    const float* Wv    = (const float*)d_in[7];
    const float* bv    = (const float*)d_in[8];
    const float* Wo    = (const float*)d_in[9];
    const float* bo    = (const float*)d_in[10];
    float* out = (float*)d_out;

    cudaFuncSetAttribute(k_attn, cudaFuncAttributeMaxDynamicSharedMemorySize,
                         SM_BYTES);

    k_qproj  <<<128, 256>>>(query, Wq, bq);           // idx 0
    k_aprep  <<<128, 128>>>(Wk, bk);                  // idx 1
    k_attn   <<<NCHUNK, 256, SM_BYTES>>>(key, value); // idx 2
    k_wreduce<<<1024, 128>>>();                       // idx 3  <- ncu window
    k_xproj  <<<512, 256>>>(Wv, bv);                  // idx 4
    k_out    <<<512, 256>>>(Wo, bo, out);             // idx 5
}